// round 13
// baseline (speedup 1.0000x reference)
#include <cuda_runtime.h>
#include <cstdint>

#define N_BATCH 8
#define K_ANCH  9
#define Hdim    120
#define Wdim    120
#define HW      (Hdim*Wdim)
#define TOT     (HW*K_ANCH)       /* 129600 */
#define PRE     3000
#define POST    300
#define NWORDS  47                /* ceil(3000/64) */
#define MPITCH  48
#define NPAIR   24
#define CAND_MAX 8192
#define NBUCKET  4096
#define HBLK     16               /* sweep blocks per batch */

// ---------------- scratch (static device globals; no allocation) ------------
__device__ float  g_topk_score[N_BATCH*PRE];
__device__ float4 g_boxes[N_BATCH*PRE];
__device__ unsigned long long g_mask[(size_t)N_BATCH*PRE*MPITCH];   // ~9.2MB
__device__ unsigned int g_hist[N_BATCH][NBUCKET];     // zeroed by thresh_kernel
__device__ unsigned int g_boff[N_BATCH][NBUCKET];     // candidates above bucket
__device__ unsigned int g_bcnt[N_BATCH][NBUCKET];     // zeroed by scan_kernel
__device__ unsigned int g_B[N_BATCH];
__device__ unsigned long long g_cand[N_BATCH][CAND_MAX];

// monotone float->uint key (descending floats -> descending uints)
__device__ __forceinline__ unsigned int fkey(float x) {
    unsigned int u = __float_as_uint(x);
    return (u & 0x80000000u) ? ~u : (u | 0x80000000u);
}
__device__ __forceinline__ float fkey_inv(unsigned int k) {
    return (k & 0x80000000u) ? __uint_as_float(k ^ 0x80000000u)
                             : __uint_as_float(~k);
}
__device__ __forceinline__ float boxarea(float4 b) {
    return __fmul_rn(__fadd_rn(__fsub_rn(b.z, b.x), 1.0f),
                     __fadd_rn(__fsub_rn(b.w, b.y), 1.0f));
}
// exact fp32 test for RN(inter/denom) > 0.5 without division (R9-proven)
__device__ __forceinline__ bool iou_gt_half(float inter, float denom) {
    float t = __fsub_rn(__fadd_rn(inter, inter), denom);
    bool pos = (t > __fmul_rn(denom, 0x1p-24f));
    return (denom > 0.0f) ? pos : ((denom == 0.0f) & (inter > 0.0f));
}

// ---------------- Stage 1a: chip-wide histogram ------------------------------
extern "C" __global__ void __launch_bounds__(256)
hist_kernel(const float* __restrict__ cls) {
    const int n = blockIdx.y;
    const float4* sc4 = (const float4*)(cls + (size_t)n * TOT);
    unsigned int* h = g_hist[n];
    for (int i = blockIdx.x*256 + threadIdx.x; i < TOT/4; i += HBLK*256) {
        float4 v = sc4[i];
        atomicAdd(&h[fkey(v.x) >> 20], 1u);
        atomicAdd(&h[fkey(v.y) >> 20], 1u);
        atomicAdd(&h[fkey(v.z) >> 20], 1u);
        atomicAdd(&h[fkey(v.w) >> 20], 1u);
    }
}

// ---------------- Stage 1b: bucket suffix-sums + threshold (+ self-clean) ---
extern "C" __global__ void __launch_bounds__(1024)
thresh_kernel() {
    const int n = blockIdx.x;
    const int tid = threadIdx.x;
    __shared__ unsigned int hist[NBUCKET];
    __shared__ unsigned int sscan[1024];
    __shared__ int sB;

    for (int b = tid; b < NBUCKET; b += 1024) hist[b] = g_hist[n][b];
    if (tid == 0) sB = 0;
    __syncthreads();

    unsigned int h0 = hist[4*tid], h1 = hist[4*tid+1],
                 h2 = hist[4*tid+2], h3 = hist[4*tid+3];
    sscan[tid] = h0 + h1 + h2 + h3;
    __syncthreads();

    // inclusive suffix scan over the 1024 group sums (Hillis-Steele)
    for (int off = 1; off < 1024; off <<= 1) {
        unsigned int v = (tid + off < 1024) ? sscan[tid + off] : 0u;
        __syncthreads();
        sscan[tid] += v;
        __syncthreads();
    }
    const unsigned int gsuf = (tid + 1 < 1024) ? sscan[tid + 1] : 0u;

    // boff[b] = # elements in buckets strictly above b
    unsigned int b3 = gsuf;
    unsigned int b2 = gsuf + h3;
    unsigned int b1 = b2 + h2;
    unsigned int b0 = b1 + h1;
    g_boff[n][4*tid+3] = b3;
    g_boff[n][4*tid+2] = b2;
    g_boff[n][4*tid+1] = b1;
    g_boff[n][4*tid+0] = b0;

    // B = max bucket with cumulative count (from top) >= PRE
    if (b0 + h0 >= PRE) atomicMax(&sB, 4*tid+0);
    if (b1 + h1 >= PRE) atomicMax(&sB, 4*tid+1);
    if (b2 + h2 >= PRE) atomicMax(&sB, 4*tid+2);
    if (b3 + h3 >= PRE) atomicMax(&sB, 4*tid+3);
    __syncthreads();
    if (tid == 0) g_B[n] = (unsigned int)sB;

    // self-clean histogram for the next graph replay
    for (int b = tid; b < NBUCKET; b += 1024) g_hist[n][b] = 0;
}

// ---------------- Stage 1c: bucket-grouped candidate compaction --------------
extern "C" __global__ void __launch_bounds__(256)
compact_kernel(const float* __restrict__ cls) {
    const int n = blockIdx.y;
    const float4* sc4 = (const float4*)(cls + (size_t)n * TOT);
    const unsigned int B = g_B[n];
    for (int i = blockIdx.x*256 + threadIdx.x; i < TOT/4; i += HBLK*256) {
        float4 v = sc4[i];
        float vv[4] = {v.x, v.y, v.z, v.w};
#pragma unroll
        for (int c = 0; c < 4; ++c) {
            unsigned int k = fkey(vv[c]);
            unsigned int b = k >> 20;
            if (b >= B) {
                unsigned int pos = g_boff[n][b] +
                                   atomicAdd(&g_bcnt[n][b], 1u);
                if (pos < CAND_MAX)
                    g_cand[n][pos] = ((unsigned long long)k << 32) |
                                     (unsigned int)(~(unsigned int)(4*i + c));
            }
        }
    }
}

// ---------------- Stage 1d+2: two-level rank + score/box scatter -------------
// rank(i) = boff[bucket] + #{j in same bucket : key_j > key_i}. Bucket spans
// are contiguous after the grouped compaction; the boundary-bucket span fits
// in L1, so intra-bucket compares are cheap. Ranks are exact & deterministic.
extern "C" __global__ void __launch_bounds__(256)
rank_kernel(const float* __restrict__ deltas) {
    const int n = blockIdx.y;
    const unsigned int B = g_B[n];
    const unsigned int total =
        min(g_boff[n][B] + g_bcnt[n][B], (unsigned)CAND_MAX);
    const unsigned int i = blockIdx.x*256 + threadIdx.x;
    if (i >= total) return;

    const unsigned long long mykey = g_cand[n][i];
    const unsigned int b = (unsigned int)(mykey >> 52);
    const unsigned int lo = g_boff[n][b];
    const unsigned int hi = min(lo + g_bcnt[n][b], (unsigned)CAND_MAX);

    unsigned int rank = lo;
    const unsigned long long* __restrict__ cand = g_cand[n];
#pragma unroll 4
    for (unsigned int j = lo; j < hi; ++j)
        rank += (cand[j] > mykey);
    if (rank >= PRE) return;

    unsigned int key = (unsigned int)(mykey >> 32);
    int o = (int)(~(unsigned int)(mykey & 0xFFFFFFFFull));
    g_topk_score[n*PRE + rank] = fkey_inv(key);

    const float ratios_[3] = {0.5f, 1.0f, 2.0f};
    const float scales_[3] = {8.0f, 16.0f, 32.0f};
    const int kk = o % K_ANCH;
    const int t0 = o / K_ANCH;
    const int ww = t0 % Wdim;
    const int hh = t0 / Wdim;

    float v[4];
#pragma unroll
    for (int jj = 0; jj < 4; ++jj) {
        int f  = ((kk*4 + jj)*Hdim + hh)*Wdim + ww;
        int j  = f & 3;
        int r1 = f >> 2;
        int k  = r1 % K_ANCH;
        int r2 = r1 / K_ANCH;
        int w  = r2 % Wdim;
        int h  = r2 / Wdim;

        float sr  = __fsqrt_rn(ratios_[k/3]);
        float wsz = __fdiv_rn(__fmul_rn(16.0f, scales_[k%3]), sr);
        float hsz = __fmul_rn(__fmul_rn(16.0f, scales_[k%3]), sr);
        float cx  = __fmul_rn(__fadd_rn((float)w, 0.5f), 16.0f);
        float cy  = __fmul_rn(__fadd_rn((float)h, 0.5f), 16.0f);

        float a;
        if      (j == 0) a = __fsub_rn(cx, __fmul_rn(0.5f, wsz));
        else if (j == 1) a = __fsub_rn(cy, __fmul_rn(0.5f, hsz));
        else if (j == 2) a = __fadd_rn(cx, __fmul_rn(0.5f, wsz));
        else             a = __fadd_rn(cy, __fmul_rn(0.5f, hsz));

        float d   = deltas[((size_t)n*36 + (k*4 + j))*HW + h*Wdim + w];
        float val = __fadd_rn(a, d);
        v[jj] = fminf(fmaxf(val, 0.0f), 1919.0f);
    }
    g_boxes[n*PRE + rank] = make_float4(v[0], v[1], v[2], v[3]);
}

// ---------------- Stage 3: NMS suppression bitmask (R9-proven) --------------
extern "C" __global__ void __launch_bounds__(256)
mask_kernel() {
    const int cb = blockIdx.y, n = blockIdx.z;
    const int sub = threadIdx.x >> 6;
    const int t   = threadIdx.x & 63;
    const int rb  = blockIdx.x*4 + sub;
    __shared__ float4 colbox[64];
    __shared__ float  colarea[64];

    if (threadIdx.x < 64) {
        int cj = cb*64 + threadIdx.x;
        float4 cbx = (cj < PRE) ? g_boxes[n*PRE + cj] : make_float4(0,0,0,0);
        colbox[threadIdx.x]  = cbx;
        colarea[threadIdx.x] = boxarea(cbx);
    }
    __syncthreads();

    if (rb > cb || rb >= NWORDS) return;
    const int i = rb*64 + t;
    if (i >= PRE) return;

    const float4 bi = g_boxes[n*PRE + i];
    const float  ai = boxarea(bi);
    const int jmax = min(64, PRE - cb*64);
    unsigned long long bits = 0ull;
    const int cstart = (rb == cb) ? (t + 1) : 0;

    for (int c = cstart; c < jmax; ++c) {
        float4 bj = colbox[c];
        float aj = colarea[c];
        float xx1 = fmaxf(bi.x, bj.x), yy1 = fmaxf(bi.y, bj.y);
        float xx2 = fminf(bi.z, bj.z), yy2 = fminf(bi.w, bj.w);
        float iw = fmaxf(__fadd_rn(__fsub_rn(xx2, xx1), 1.0f), 0.0f);
        float ih = fmaxf(__fadd_rn(__fsub_rn(yy2, yy1), 1.0f), 0.0f);
        float inter = __fmul_rn(iw, ih);
        float denom = __fsub_rn(__fadd_rn(ai, aj), inter);
        if (iou_gt_half(inter, denom)) bits |= (1ull << c);
    }
    g_mask[((size_t)n*PRE + i)*MPITCH + cb] = bits;
}

// ---------------- Stage 4: lazy scan, 4 warps/batch (R10-proven) -------------
// Also self-cleans g_bcnt[n] for the next graph replay (runs after rank).
extern "C" __global__ void __launch_bounds__(128)
scan_kernel(float* __restrict__ out) {
    const int n = blockIdx.x;
    const int tid  = threadIdx.x;
    const int lane = tid & 31;
    const int wid  = tid >> 5;
    __shared__ ulonglong2 s_diag[2][128];
    __shared__ ulonglong2 s_accw[4];
    __shared__ int s_kept[POST];
    __shared__ int s_nk;
    const unsigned FULL = 0xffffffffu;

    // self-clean bucket counters for next replay
    for (int b = tid; b < NBUCKET; b += 128) g_bcnt[n][b] = 0;

    const unsigned long long* __restrict__ mbase =
        g_mask + (size_t)n * PRE * MPITCH;

    s_diag[0][tid] = *(const ulonglong2*)(mbase + (size_t)tid * MPITCH);

    int nk = 0;
    for (int t = 0; t < NPAIR && nk < POST; ++t) {
        const int cb = t & 1, pb = cb ^ 1;
        const int w2 = 2*t;

        if (t + 1 < NPAIR) {
            int r = 128*(t+1) + tid;
            ulonglong2 d = make_ulonglong2(0ull, 0ull);
            if (r < PRE)
                d = *(const ulonglong2*)(mbase + (size_t)r * MPITCH + (w2+2));
            s_diag[pb][tid] = d;
        }

        unsigned long long gx = 0ull, gy = 0ull;
        for (int j = tid; j < nk; j += 128) {
            ulonglong2 m = *(const ulonglong2*)
                (mbase + (size_t)s_kept[j] * MPITCH + w2);
            gx |= m.x; gy |= m.y;
        }
#pragma unroll
        for (int off = 16; off; off >>= 1) {
            gx |= __shfl_xor_sync(FULL, gx, off);
            gy |= __shfl_xor_sync(FULL, gy, off);
        }
        if (lane == 0) s_accw[wid] = make_ulonglong2(gx, gy);
        __syncthreads();

        if (wid == 0) {
            unsigned long long a0 =
                s_accw[0].x | s_accw[1].x | s_accw[2].x | s_accw[3].x;
            unsigned long long a1 =
                s_accw[0].y | s_accw[1].y | s_accw[2].y | s_accw[3].y;
            unsigned long long f0 = (w2   == NWORDS-1) ? ((1ull<<56)-1ull)
                                  : (w2   <  NWORDS  ) ? ~0ull : 0ull;
            unsigned long long f1 = (w2+1 == NWORDS-1) ? ((1ull<<56)-1ull)
                                  : (w2+1 <  NWORDS  ) ? ~0ull : 0ull;
            unsigned long long c0 = f0 & ~a0;
            unsigned long long c1 = f1 & ~a1;

            const int base = 128*t;
            int k = nk;
            while ((c0 | c1) && k < POST) {
                if (c0) {
                    int b = __ffsll((long long)c0) - 1;
                    s_kept[k] = base + b;
                    ++k;
                    c0 &= ~(1ull << b);
                    ulonglong2 d = s_diag[cb][b];
                    c0 &= ~d.x;
                    c1 &= ~d.y;
                } else {
                    int b = __ffsll((long long)c1) - 1;
                    s_kept[k] = base + 64 + b;
                    ++k;
                    c1 &= ~(1ull << b);
                    ulonglong2 d = s_diag[cb][64 + b];
                    c1 &= ~d.y;
                }
            }
            if (lane == 0) s_nk = k;
        }
        __syncthreads();
        nk = s_nk;
    }

    for (int r = tid; r < POST; r += 128) {
        float x1 = 0.0f, y1 = 0.0f, x2 = 0.0f, y2 = 0.0f;
        if (r < nk) {
            int i = s_kept[r];
            float4 b = g_boxes[n*PRE + i];
            x1 = b.x; y1 = b.y; x2 = b.z; y2 = b.w;
        }
        float* o = out + (size_t)(n*POST + r)*5;
        o[1] = x1; o[2] = y1; o[3] = x2; o[4] = y2;
    }

    if (n == 7) {
        for (int r = tid; r < POST; r += 128) {
            float sc = (r < nk) ? g_topk_score[7*PRE + s_kept[r]] : 0.0f;
#pragma unroll
            for (int nn = 0; nn < N_BATCH; ++nn)
                out[(size_t)(nn*POST + r)*5] = sc;
        }
    }
}

// ---------------- launch -----------------------------------------------------
extern "C" void kernel_launch(void* const* d_in, const int* in_sizes, int n_in,
                              void* d_out, int out_size) {
    const float* cls;
    const float* deltas;
    if (in_sizes[0] == N_BATCH*K_ANCH*HW) {     // 1,036,800
        cls = (const float*)d_in[0]; deltas = (const float*)d_in[1];
    } else {
        cls = (const float*)d_in[1]; deltas = (const float*)d_in[0];
    }
    float* out = (float*)d_out;

    hist_kernel<<<dim3(HBLK, N_BATCH), 256>>>(cls);
    thresh_kernel<<<N_BATCH, 1024>>>();
    compact_kernel<<<dim3(HBLK, N_BATCH), 256>>>(cls);
    rank_kernel<<<dim3(CAND_MAX/256, N_BATCH), 256>>>(deltas);
    dim3 mg((NWORDS + 3)/4, NWORDS, N_BATCH);
    mask_kernel<<<mg, 256>>>();
    scan_kernel<<<N_BATCH, 128>>>(out);
}

// round 14
// speedup vs baseline: 1.2491x; 1.2491x over previous
#include <cuda_runtime.h>
#include <cstdint>

#define N_BATCH 8
#define K_ANCH  9
#define Hdim    120
#define Wdim    120
#define HW      (Hdim*Wdim)
#define TOT     (HW*K_ANCH)       /* 129600 */
#define PRE     3000
#define POST    300
#define NWORDS  47                /* ceil(3000/64) */
#define MPITCH  48
#define NPAIR   24
#define CAND_MAX 8192
#define NBUCKET  4096
#define HBLK     16               /* sweep blocks per batch */

// ---------------- scratch (static device globals; no allocation) ------------
__device__ float  g_topk_score[N_BATCH*PRE];
__device__ float4 g_boxes[N_BATCH*PRE];
__device__ unsigned long long g_mask[(size_t)N_BATCH*PRE*MPITCH];   // ~9.2MB
__device__ unsigned int g_hist[N_BATCH][NBUCKET];     // zeroed by thresh_kernel
__device__ unsigned int g_boff[N_BATCH][NBUCKET];     // candidates above bucket
__device__ unsigned int g_bcnt[N_BATCH][NBUCKET];     // zeroed by scan_kernel
__device__ unsigned int g_B[N_BATCH];
__device__ unsigned long long g_cand[N_BATCH][CAND_MAX];

// monotone float->uint key (descending floats -> descending uints)
__device__ __forceinline__ unsigned int fkey(float x) {
    unsigned int u = __float_as_uint(x);
    return (u & 0x80000000u) ? ~u : (u | 0x80000000u);
}
__device__ __forceinline__ float fkey_inv(unsigned int k) {
    return (k & 0x80000000u) ? __uint_as_float(k ^ 0x80000000u)
                             : __uint_as_float(~k);
}
__device__ __forceinline__ float boxarea(float4 b) {
    return __fmul_rn(__fadd_rn(__fsub_rn(b.z, b.x), 1.0f),
                     __fadd_rn(__fsub_rn(b.w, b.y), 1.0f));
}
// exact fp32 test for RN(inter/denom) > 0.5 without division (R9-proven)
__device__ __forceinline__ bool iou_gt_half(float inter, float denom) {
    float t = __fsub_rn(__fadd_rn(inter, inter), denom);
    bool pos = (t > __fmul_rn(denom, 0x1p-24f));
    return (denom > 0.0f) ? pos : ((denom == 0.0f) & (inter > 0.0f));
}

// ---------------- Stage 1a: chip-wide histogram ------------------------------
extern "C" __global__ void __launch_bounds__(256)
hist_kernel(const float* __restrict__ cls) {
    const int n = blockIdx.y;
    const float4* sc4 = (const float4*)(cls + (size_t)n * TOT);
    unsigned int* h = g_hist[n];
    for (int i = blockIdx.x*256 + threadIdx.x; i < TOT/4; i += HBLK*256) {
        float4 v = sc4[i];
        atomicAdd(&h[fkey(v.x) >> 20], 1u);
        atomicAdd(&h[fkey(v.y) >> 20], 1u);
        atomicAdd(&h[fkey(v.z) >> 20], 1u);
        atomicAdd(&h[fkey(v.w) >> 20], 1u);
    }
}

// ---------------- Stage 1b: bucket suffix-sums + threshold (+ self-clean) ---
extern "C" __global__ void __launch_bounds__(1024)
thresh_kernel() {
    const int n = blockIdx.x;
    const int tid = threadIdx.x;
    __shared__ unsigned int hist[NBUCKET];
    __shared__ unsigned int sscan[1024];
    __shared__ int sB;

    for (int b = tid; b < NBUCKET; b += 1024) hist[b] = g_hist[n][b];
    if (tid == 0) sB = 0;
    __syncthreads();

    unsigned int h0 = hist[4*tid], h1 = hist[4*tid+1],
                 h2 = hist[4*tid+2], h3 = hist[4*tid+3];
    sscan[tid] = h0 + h1 + h2 + h3;
    __syncthreads();

    // inclusive suffix scan over the 1024 group sums (Hillis-Steele)
    for (int off = 1; off < 1024; off <<= 1) {
        unsigned int v = (tid + off < 1024) ? sscan[tid + off] : 0u;
        __syncthreads();
        sscan[tid] += v;
        __syncthreads();
    }
    const unsigned int gsuf = (tid + 1 < 1024) ? sscan[tid + 1] : 0u;

    // boff[b] = # elements in buckets strictly above b
    unsigned int b3 = gsuf;
    unsigned int b2 = gsuf + h3;
    unsigned int b1 = b2 + h2;
    unsigned int b0 = b1 + h1;
    g_boff[n][4*tid+3] = b3;
    g_boff[n][4*tid+2] = b2;
    g_boff[n][4*tid+1] = b1;
    g_boff[n][4*tid+0] = b0;

    // B = max bucket with cumulative count (from top) >= PRE
    if (b0 + h0 >= PRE) atomicMax(&sB, 4*tid+0);
    if (b1 + h1 >= PRE) atomicMax(&sB, 4*tid+1);
    if (b2 + h2 >= PRE) atomicMax(&sB, 4*tid+2);
    if (b3 + h3 >= PRE) atomicMax(&sB, 4*tid+3);
    __syncthreads();
    if (tid == 0) g_B[n] = (unsigned int)sB;

    // self-clean histogram for the next graph replay
    for (int b = tid; b < NBUCKET; b += 1024) g_hist[n][b] = 0;
}

// ---------------- Stage 1c: bucket-grouped candidate compaction --------------
extern "C" __global__ void __launch_bounds__(256)
compact_kernel(const float* __restrict__ cls) {
    const int n = blockIdx.y;
    const float4* sc4 = (const float4*)(cls + (size_t)n * TOT);
    const unsigned int B = g_B[n];
    for (int i = blockIdx.x*256 + threadIdx.x; i < TOT/4; i += HBLK*256) {
        float4 v = sc4[i];
        float vv[4] = {v.x, v.y, v.z, v.w};
#pragma unroll
        for (int c = 0; c < 4; ++c) {
            unsigned int k = fkey(vv[c]);
            unsigned int b = k >> 20;
            if (b >= B) {
                unsigned int pos = g_boff[n][b] +
                                   atomicAdd(&g_bcnt[n][b], 1u);
                if (pos < CAND_MAX)
                    g_cand[n][pos] = ((unsigned long long)k << 32) |
                                     (unsigned int)(~(unsigned int)(4*i + c));
            }
        }
    }
}

// ---------------- Stage 1d+2: warp-per-candidate rank + score/box scatter ----
// rank(i) = boff[bucket] + #{j in same bucket : key_j > key_i}. One WARP per
// candidate: lanes stride the (contiguous) bucket span with coalesced loads,
// per-lane counts combined by one __reduce_add_sync. Lane 0 writes the score
// and computes/scatters the box. Exact and deterministic.
extern "C" __global__ void __launch_bounds__(256)
rank_kernel(const float* __restrict__ deltas) {
    const int n = blockIdx.y;
    const unsigned int B = g_B[n];
    const unsigned int total =
        min(g_boff[n][B] + g_bcnt[n][B], (unsigned)CAND_MAX);
    const unsigned int ci = blockIdx.x*8 + (threadIdx.x >> 5); // warp -> cand
    if (ci >= total) return;
    const int lane = threadIdx.x & 31;
    const unsigned FULL = 0xffffffffu;

    const unsigned long long* __restrict__ cand = g_cand[n];
    const unsigned long long mykey = cand[ci];          // broadcast load
    const unsigned int b  = (unsigned int)(mykey >> 52);
    const unsigned int lo = g_boff[n][b];
    const unsigned int hi = min(lo + g_bcnt[n][b], (unsigned)CAND_MAX);

    int c = 0;
    for (unsigned int j = lo + lane; j < hi; j += 32)
        c += (cand[j] > mykey);
    unsigned int rank = lo + __reduce_add_sync(FULL, c);
    if (rank >= PRE || lane != 0) return;

    unsigned int key = (unsigned int)(mykey >> 32);
    int o = (int)(~(unsigned int)(mykey & 0xFFFFFFFFull));
    g_topk_score[n*PRE + rank] = fkey_inv(key);

    const float ratios_[3] = {0.5f, 1.0f, 2.0f};
    const float scales_[3] = {8.0f, 16.0f, 32.0f};
    const int kk = o % K_ANCH;
    const int t0 = o / K_ANCH;
    const int ww = t0 % Wdim;
    const int hh = t0 / Wdim;

    float v[4];
#pragma unroll
    for (int jj = 0; jj < 4; ++jj) {
        int f  = ((kk*4 + jj)*Hdim + hh)*Wdim + ww;
        int j  = f & 3;
        int r1 = f >> 2;
        int k  = r1 % K_ANCH;
        int r2 = r1 / K_ANCH;
        int w  = r2 % Wdim;
        int h  = r2 / Wdim;

        float sr  = __fsqrt_rn(ratios_[k/3]);
        float wsz = __fdiv_rn(__fmul_rn(16.0f, scales_[k%3]), sr);
        float hsz = __fmul_rn(__fmul_rn(16.0f, scales_[k%3]), sr);
        float cx  = __fmul_rn(__fadd_rn((float)w, 0.5f), 16.0f);
        float cy  = __fmul_rn(__fadd_rn((float)h, 0.5f), 16.0f);

        float a;
        if      (j == 0) a = __fsub_rn(cx, __fmul_rn(0.5f, wsz));
        else if (j == 1) a = __fsub_rn(cy, __fmul_rn(0.5f, hsz));
        else if (j == 2) a = __fadd_rn(cx, __fmul_rn(0.5f, wsz));
        else             a = __fadd_rn(cy, __fmul_rn(0.5f, hsz));

        float d   = deltas[((size_t)n*36 + (k*4 + j))*HW + h*Wdim + w];
        float val = __fadd_rn(a, d);
        v[jj] = fminf(fmaxf(val, 0.0f), 1919.0f);
    }
    g_boxes[n*PRE + rank] = make_float4(v[0], v[1], v[2], v[3]);
}

// ---------------- Stage 3: NMS suppression bitmask (R9-proven) --------------
extern "C" __global__ void __launch_bounds__(256)
mask_kernel() {
    const int cb = blockIdx.y, n = blockIdx.z;
    const int sub = threadIdx.x >> 6;
    const int t   = threadIdx.x & 63;
    const int rb  = blockIdx.x*4 + sub;
    __shared__ float4 colbox[64];
    __shared__ float  colarea[64];

    if (threadIdx.x < 64) {
        int cj = cb*64 + threadIdx.x;
        float4 cbx = (cj < PRE) ? g_boxes[n*PRE + cj] : make_float4(0,0,0,0);
        colbox[threadIdx.x]  = cbx;
        colarea[threadIdx.x] = boxarea(cbx);
    }
    __syncthreads();

    if (rb > cb || rb >= NWORDS) return;
    const int i = rb*64 + t;
    if (i >= PRE) return;

    const float4 bi = g_boxes[n*PRE + i];
    const float  ai = boxarea(bi);
    const int jmax = min(64, PRE - cb*64);
    unsigned long long bits = 0ull;
    const int cstart = (rb == cb) ? (t + 1) : 0;

    for (int c = cstart; c < jmax; ++c) {
        float4 bj = colbox[c];
        float aj = colarea[c];
        float xx1 = fmaxf(bi.x, bj.x), yy1 = fmaxf(bi.y, bj.y);
        float xx2 = fminf(bi.z, bj.z), yy2 = fminf(bi.w, bj.w);
        float iw = fmaxf(__fadd_rn(__fsub_rn(xx2, xx1), 1.0f), 0.0f);
        float ih = fmaxf(__fadd_rn(__fsub_rn(yy2, yy1), 1.0f), 0.0f);
        float inter = __fmul_rn(iw, ih);
        float denom = __fsub_rn(__fadd_rn(ai, aj), inter);
        if (iou_gt_half(inter, denom)) bits |= (1ull << c);
    }
    g_mask[((size_t)n*PRE + i)*MPITCH + cb] = bits;
}

// ---------------- Stage 4: lazy scan, 4 warps/batch (R10-proven) -------------
// Also self-cleans g_bcnt[n] for the next graph replay (runs after rank).
extern "C" __global__ void __launch_bounds__(128)
scan_kernel(float* __restrict__ out) {
    const int n = blockIdx.x;
    const int tid  = threadIdx.x;
    const int lane = tid & 31;
    const int wid  = tid >> 5;
    __shared__ ulonglong2 s_diag[2][128];
    __shared__ ulonglong2 s_accw[4];
    __shared__ int s_kept[POST];
    __shared__ int s_nk;
    const unsigned FULL = 0xffffffffu;

    // self-clean bucket counters for next replay
    for (int b = tid; b < NBUCKET; b += 128) g_bcnt[n][b] = 0;

    const unsigned long long* __restrict__ mbase =
        g_mask + (size_t)n * PRE * MPITCH;

    s_diag[0][tid] = *(const ulonglong2*)(mbase + (size_t)tid * MPITCH);

    int nk = 0;
    for (int t = 0; t < NPAIR && nk < POST; ++t) {
        const int cb = t & 1, pb = cb ^ 1;
        const int w2 = 2*t;

        if (t + 1 < NPAIR) {
            int r = 128*(t+1) + tid;
            ulonglong2 d = make_ulonglong2(0ull, 0ull);
            if (r < PRE)
                d = *(const ulonglong2*)(mbase + (size_t)r * MPITCH + (w2+2));
            s_diag[pb][tid] = d;
        }

        unsigned long long gx = 0ull, gy = 0ull;
        for (int j = tid; j < nk; j += 128) {
            ulonglong2 m = *(const ulonglong2*)
                (mbase + (size_t)s_kept[j] * MPITCH + w2);
            gx |= m.x; gy |= m.y;
        }
#pragma unroll
        for (int off = 16; off; off >>= 1) {
            gx |= __shfl_xor_sync(FULL, gx, off);
            gy |= __shfl_xor_sync(FULL, gy, off);
        }
        if (lane == 0) s_accw[wid] = make_ulonglong2(gx, gy);
        __syncthreads();

        if (wid == 0) {
            unsigned long long a0 =
                s_accw[0].x | s_accw[1].x | s_accw[2].x | s_accw[3].x;
            unsigned long long a1 =
                s_accw[0].y | s_accw[1].y | s_accw[2].y | s_accw[3].y;
            unsigned long long f0 = (w2   == NWORDS-1) ? ((1ull<<56)-1ull)
                                  : (w2   <  NWORDS  ) ? ~0ull : 0ull;
            unsigned long long f1 = (w2+1 == NWORDS-1) ? ((1ull<<56)-1ull)
                                  : (w2+1 <  NWORDS  ) ? ~0ull : 0ull;
            unsigned long long c0 = f0 & ~a0;
            unsigned long long c1 = f1 & ~a1;

            const int base = 128*t;
            int k = nk;
            while ((c0 | c1) && k < POST) {
                if (c0) {
                    int b = __ffsll((long long)c0) - 1;
                    s_kept[k] = base + b;
                    ++k;
                    c0 &= ~(1ull << b);
                    ulonglong2 d = s_diag[cb][b];
                    c0 &= ~d.x;
                    c1 &= ~d.y;
                } else {
                    int b = __ffsll((long long)c1) - 1;
                    s_kept[k] = base + 64 + b;
                    ++k;
                    c1 &= ~(1ull << b);
                    ulonglong2 d = s_diag[cb][64 + b];
                    c1 &= ~d.y;
                }
            }
            if (lane == 0) s_nk = k;
        }
        __syncthreads();
        nk = s_nk;
    }

    for (int r = tid; r < POST; r += 128) {
        float x1 = 0.0f, y1 = 0.0f, x2 = 0.0f, y2 = 0.0f;
        if (r < nk) {
            int i = s_kept[r];
            float4 b = g_boxes[n*PRE + i];
            x1 = b.x; y1 = b.y; x2 = b.z; y2 = b.w;
        }
        float* o = out + (size_t)(n*POST + r)*5;
        o[1] = x1; o[2] = y1; o[3] = x2; o[4] = y2;
    }

    if (n == 7) {
        for (int r = tid; r < POST; r += 128) {
            float sc = (r < nk) ? g_topk_score[7*PRE + s_kept[r]] : 0.0f;
#pragma unroll
            for (int nn = 0; nn < N_BATCH; ++nn)
                out[(size_t)(nn*POST + r)*5] = sc;
        }
    }
}

// ---------------- launch -----------------------------------------------------
extern "C" void kernel_launch(void* const* d_in, const int* in_sizes, int n_in,
                              void* d_out, int out_size) {
    const float* cls;
    const float* deltas;
    if (in_sizes[0] == N_BATCH*K_ANCH*HW) {     // 1,036,800
        cls = (const float*)d_in[0]; deltas = (const float*)d_in[1];
    } else {
        cls = (const float*)d_in[1]; deltas = (const float*)d_in[0];
    }
    float* out = (float*)d_out;

    hist_kernel<<<dim3(HBLK, N_BATCH), 256>>>(cls);
    thresh_kernel<<<N_BATCH, 1024>>>();
    compact_kernel<<<dim3(HBLK, N_BATCH), 256>>>(cls);
    rank_kernel<<<dim3(CAND_MAX/8, N_BATCH), 256>>>(deltas);
    dim3 mg((NWORDS + 3)/4, NWORDS, N_BATCH);
    mask_kernel<<<mg, 256>>>();
    scan_kernel<<<N_BATCH, 128>>>(out);
}

// round 15
// speedup vs baseline: 1.2596x; 1.0084x over previous
#include <cuda_runtime.h>
#include <cstdint>

#define N_BATCH 8
#define K_ANCH  9
#define Hdim    120
#define Wdim    120
#define HW      (Hdim*Wdim)
#define TOT     (HW*K_ANCH)       /* 129600 */
#define PRE     3000
#define POST    300
#define NWORDS  47                /* ceil(3000/64) */
#define MPITCH  48
#define NPAIR   24
#define CAND_MAX 8192
#define NBUCKET  4096
#define HBLK     16               /* sweep blocks per batch */

// ---------------- scratch (static device globals; no allocation) ------------
__device__ float  g_topk_score[N_BATCH*PRE];
__device__ float4 g_boxes[N_BATCH*PRE];
__device__ unsigned long long g_mask[(size_t)N_BATCH*PRE*MPITCH];   // ~9.2MB
__device__ unsigned int g_hist[N_BATCH][NBUCKET];     // zeroed by scan_kernel
__device__ unsigned int g_boff[N_BATCH][NBUCKET];     // written by compact blk0
__device__ unsigned int g_bcnt[N_BATCH][NBUCKET];     // zeroed by scan_kernel
__device__ unsigned int g_B[N_BATCH];
__device__ unsigned long long g_cand[N_BATCH][CAND_MAX];

// monotone float->uint key (descending floats -> descending uints)
__device__ __forceinline__ unsigned int fkey(float x) {
    unsigned int u = __float_as_uint(x);
    return (u & 0x80000000u) ? ~u : (u | 0x80000000u);
}
__device__ __forceinline__ float fkey_inv(unsigned int k) {
    return (k & 0x80000000u) ? __uint_as_float(k ^ 0x80000000u)
                             : __uint_as_float(~k);
}
__device__ __forceinline__ float boxarea(float4 b) {
    return __fmul_rn(__fadd_rn(__fsub_rn(b.z, b.x), 1.0f),
                     __fadd_rn(__fsub_rn(b.w, b.y), 1.0f));
}
// exact fp32 test for RN(inter/denom) > 0.5 without division (R9-proven)
__device__ __forceinline__ bool iou_gt_half(float inter, float denom) {
    float t = __fsub_rn(__fadd_rn(inter, inter), denom);
    bool pos = (t > __fmul_rn(denom, 0x1p-24f));
    return (denom > 0.0f) ? pos : ((denom == 0.0f) & (inter > 0.0f));
}

// ---------------- Stage 1a: chip-wide histogram ------------------------------
extern "C" __global__ void __launch_bounds__(256)
hist_kernel(const float* __restrict__ cls) {
    const int n = blockIdx.y;
    const float4* sc4 = (const float4*)(cls + (size_t)n * TOT);
    unsigned int* h = g_hist[n];
    for (int i = blockIdx.x*256 + threadIdx.x; i < TOT/4; i += HBLK*256) {
        float4 v = sc4[i];
        atomicAdd(&h[fkey(v.x) >> 20], 1u);
        atomicAdd(&h[fkey(v.y) >> 20], 1u);
        atomicAdd(&h[fkey(v.z) >> 20], 1u);
        atomicAdd(&h[fkey(v.w) >> 20], 1u);
    }
}

// ---------------- Stage 1b+1c: per-block threshold + grouped compaction ------
// Every block recomputes (B, boff) from the histogram in smem (cheap, fully
// parallel); block (0,n) publishes them for rank_kernel. Candidates are
// scattered grouped by bucket: slot = boff[b] + atomicAdd(bcnt[b]).
extern "C" __global__ void __launch_bounds__(256)
compact_kernel(const float* __restrict__ cls) {
    const int n   = blockIdx.y;
    const int tid = threadIdx.x;
    __shared__ unsigned int sh_boff[NBUCKET];    // 16KB
    __shared__ unsigned int part[256];
    __shared__ int sB;

    // load 16 buckets/thread
    unsigned int h[16];
    const unsigned int base = tid * 16;
#pragma unroll
    for (int q = 0; q < 16; ++q) h[q] = g_hist[n][base + q];
    unsigned int gsum = 0;
#pragma unroll
    for (int q = 0; q < 16; ++q) gsum += h[q];
    part[tid] = gsum;
    if (tid == 0) sB = 0;
    __syncthreads();

    // inclusive suffix scan over 256 group sums (Hillis-Steele)
    for (int off = 1; off < 256; off <<= 1) {
        unsigned int v = (tid + off < 256) ? part[tid + off] : 0u;
        __syncthreads();
        part[tid] += v;
        __syncthreads();
    }
    unsigned int run = (tid + 1 < 256) ? part[tid + 1] : 0u;  // above my group
#pragma unroll
    for (int q = 15; q >= 0; --q) {
        sh_boff[base + q] = run;                 // strictly above bucket
        if (run + h[q] >= PRE) atomicMax(&sB, (int)(base + q));
        run += h[q];
    }
    __syncthreads();
    const unsigned int B = (unsigned int)sB;

    if (blockIdx.x == 0) {                       // publish for rank_kernel
        for (int b = tid; b < NBUCKET; b += 256) g_boff[n][b] = sh_boff[b];
        if (tid == 0) g_B[n] = B;
    }

    const float4* sc4 = (const float4*)(cls + (size_t)n * TOT);
    for (int i = blockIdx.x*256 + tid; i < TOT/4; i += HBLK*256) {
        float4 v = sc4[i];
        float vv[4] = {v.x, v.y, v.z, v.w};
#pragma unroll
        for (int c = 0; c < 4; ++c) {
            unsigned int k = fkey(vv[c]);
            unsigned int b = k >> 20;
            if (b >= B) {
                unsigned int pos = sh_boff[b] + atomicAdd(&g_bcnt[n][b], 1u);
                if (pos < CAND_MAX)
                    g_cand[n][pos] = ((unsigned long long)k << 32) |
                                     (unsigned int)(~(unsigned int)(4*i + c));
            }
        }
    }
}

// ---------------- Stage 1d+2: warp-per-candidate rank (4x unrolled) ----------
extern "C" __global__ void __launch_bounds__(256)
rank_kernel(const float* __restrict__ deltas) {
    const int n = blockIdx.y;
    const unsigned int B = g_B[n];
    const unsigned int total =
        min(g_boff[n][B] + g_bcnt[n][B], (unsigned)CAND_MAX);
    const unsigned int ci = blockIdx.x*8 + (threadIdx.x >> 5); // warp -> cand
    if (ci >= total) return;
    const int lane = threadIdx.x & 31;
    const unsigned FULL = 0xffffffffu;

    const unsigned long long* __restrict__ cand = g_cand[n];
    const unsigned long long mykey = cand[ci];          // broadcast load
    const unsigned int b  = (unsigned int)(mykey >> 52);
    const unsigned int lo = g_boff[n][b];
    const unsigned int hi = min(lo + g_bcnt[n][b], (unsigned)CAND_MAX);

    int c = 0;
    unsigned int j = lo + lane;
    for (; j + 96 < hi; j += 128) {             // 4 independent loads (MLP=4)
        c += (cand[j     ] > mykey);
        c += (cand[j + 32] > mykey);
        c += (cand[j + 64] > mykey);
        c += (cand[j + 96] > mykey);
    }
    for (; j < hi; j += 32) c += (cand[j] > mykey);
    unsigned int rank = lo + __reduce_add_sync(FULL, c);
    if (rank >= PRE || lane != 0) return;

    unsigned int key = (unsigned int)(mykey >> 32);
    int o = (int)(~(unsigned int)(mykey & 0xFFFFFFFFull));
    g_topk_score[n*PRE + rank] = fkey_inv(key);

    const float ratios_[3] = {0.5f, 1.0f, 2.0f};
    const float scales_[3] = {8.0f, 16.0f, 32.0f};
    const int kk = o % K_ANCH;
    const int t0 = o / K_ANCH;
    const int ww = t0 % Wdim;
    const int hh = t0 / Wdim;

    float v[4];
#pragma unroll
    for (int jj = 0; jj < 4; ++jj) {
        int f  = ((kk*4 + jj)*Hdim + hh)*Wdim + ww;
        int jq = f & 3;
        int r1 = f >> 2;
        int k  = r1 % K_ANCH;
        int r2 = r1 / K_ANCH;
        int w  = r2 % Wdim;
        int hq = r2 / Wdim;

        float sr  = __fsqrt_rn(ratios_[k/3]);
        float wsz = __fdiv_rn(__fmul_rn(16.0f, scales_[k%3]), sr);
        float hsz = __fmul_rn(__fmul_rn(16.0f, scales_[k%3]), sr);
        float cx  = __fmul_rn(__fadd_rn((float)w, 0.5f), 16.0f);
        float cy  = __fmul_rn(__fadd_rn((float)hq, 0.5f), 16.0f);

        float a;
        if      (jq == 0) a = __fsub_rn(cx, __fmul_rn(0.5f, wsz));
        else if (jq == 1) a = __fsub_rn(cy, __fmul_rn(0.5f, hsz));
        else if (jq == 2) a = __fadd_rn(cx, __fmul_rn(0.5f, wsz));
        else              a = __fadd_rn(cy, __fmul_rn(0.5f, hsz));

        float d   = deltas[((size_t)n*36 + (k*4 + jq))*HW + hq*Wdim + w];
        float val = __fadd_rn(a, d);
        v[jj] = fminf(fmaxf(val, 0.0f), 1919.0f);
    }
    g_boxes[n*PRE + rank] = make_float4(v[0], v[1], v[2], v[3]);
}

// ---------------- Stage 3: NMS suppression bitmask (R9-proven) --------------
extern "C" __global__ void __launch_bounds__(256)
mask_kernel() {
    const int cb = blockIdx.y, n = blockIdx.z;
    const int sub = threadIdx.x >> 6;
    const int t   = threadIdx.x & 63;
    const int rb  = blockIdx.x*4 + sub;
    __shared__ float4 colbox[64];
    __shared__ float  colarea[64];

    if (threadIdx.x < 64) {
        int cj = cb*64 + threadIdx.x;
        float4 cbx = (cj < PRE) ? g_boxes[n*PRE + cj] : make_float4(0,0,0,0);
        colbox[threadIdx.x]  = cbx;
        colarea[threadIdx.x] = boxarea(cbx);
    }
    __syncthreads();

    if (rb > cb || rb >= NWORDS) return;
    const int i = rb*64 + t;
    if (i >= PRE) return;

    const float4 bi = g_boxes[n*PRE + i];
    const float  ai = boxarea(bi);
    const int jmax = min(64, PRE - cb*64);
    unsigned long long bits = 0ull;
    const int cstart = (rb == cb) ? (t + 1) : 0;

    for (int c = cstart; c < jmax; ++c) {
        float4 bj = colbox[c];
        float aj = colarea[c];
        float xx1 = fmaxf(bi.x, bj.x), yy1 = fmaxf(bi.y, bj.y);
        float xx2 = fminf(bi.z, bj.z), yy2 = fminf(bi.w, bj.w);
        float iw = fmaxf(__fadd_rn(__fsub_rn(xx2, xx1), 1.0f), 0.0f);
        float ih = fmaxf(__fadd_rn(__fsub_rn(yy2, yy1), 1.0f), 0.0f);
        float inter = __fmul_rn(iw, ih);
        float denom = __fsub_rn(__fadd_rn(ai, aj), inter);
        if (iou_gt_half(inter, denom)) bits |= (1ull << c);
    }
    g_mask[((size_t)n*PRE + i)*MPITCH + cb] = bits;
}

// ---------------- Stage 4: lazy scan, 4 warps/batch (R10-proven) -------------
// Also self-cleans g_bcnt[n] and g_hist[n] for the next graph replay.
extern "C" __global__ void __launch_bounds__(128)
scan_kernel(float* __restrict__ out) {
    const int n = blockIdx.x;
    const int tid  = threadIdx.x;
    const int lane = tid & 31;
    const int wid  = tid >> 5;
    __shared__ ulonglong2 s_diag[2][128];
    __shared__ ulonglong2 s_accw[4];
    __shared__ int s_kept[POST];
    __shared__ int s_nk;
    const unsigned FULL = 0xffffffffu;

    // self-clean counters/hist for next replay
    for (int b = tid; b < NBUCKET; b += 128) {
        g_bcnt[n][b] = 0;
        g_hist[n][b] = 0;
    }

    const unsigned long long* __restrict__ mbase =
        g_mask + (size_t)n * PRE * MPITCH;

    s_diag[0][tid] = *(const ulonglong2*)(mbase + (size_t)tid * MPITCH);

    int nk = 0;
    for (int t = 0; t < NPAIR && nk < POST; ++t) {
        const int cb = t & 1, pb = cb ^ 1;
        const int w2 = 2*t;

        if (t + 1 < NPAIR) {
            int r = 128*(t+1) + tid;
            ulonglong2 d = make_ulonglong2(0ull, 0ull);
            if (r < PRE)
                d = *(const ulonglong2*)(mbase + (size_t)r * MPITCH + (w2+2));
            s_diag[pb][tid] = d;
        }

        unsigned long long gx = 0ull, gy = 0ull;
        for (int j = tid; j < nk; j += 128) {
            ulonglong2 m = *(const ulonglong2*)
                (mbase + (size_t)s_kept[j] * MPITCH + w2);
            gx |= m.x; gy |= m.y;
        }
#pragma unroll
        for (int off = 16; off; off >>= 1) {
            gx |= __shfl_xor_sync(FULL, gx, off);
            gy |= __shfl_xor_sync(FULL, gy, off);
        }
        if (lane == 0) s_accw[wid] = make_ulonglong2(gx, gy);
        __syncthreads();

        if (wid == 0) {
            unsigned long long a0 =
                s_accw[0].x | s_accw[1].x | s_accw[2].x | s_accw[3].x;
            unsigned long long a1 =
                s_accw[0].y | s_accw[1].y | s_accw[2].y | s_accw[3].y;
            unsigned long long f0 = (w2   == NWORDS-1) ? ((1ull<<56)-1ull)
                                  : (w2   <  NWORDS  ) ? ~0ull : 0ull;
            unsigned long long f1 = (w2+1 == NWORDS-1) ? ((1ull<<56)-1ull)
                                  : (w2+1 <  NWORDS  ) ? ~0ull : 0ull;
            unsigned long long c0 = f0 & ~a0;
            unsigned long long c1 = f1 & ~a1;

            const int base = 128*t;
            int k = nk;
            while ((c0 | c1) && k < POST) {
                if (c0) {
                    int b = __ffsll((long long)c0) - 1;
                    s_kept[k] = base + b;
                    ++k;
                    c0 &= ~(1ull << b);
                    ulonglong2 d = s_diag[cb][b];
                    c0 &= ~d.x;
                    c1 &= ~d.y;
                } else {
                    int b = __ffsll((long long)c1) - 1;
                    s_kept[k] = base + 64 + b;
                    ++k;
                    c1 &= ~(1ull << b);
                    ulonglong2 d = s_diag[cb][64 + b];
                    c1 &= ~d.y;
                }
            }
            if (lane == 0) s_nk = k;
        }
        __syncthreads();
        nk = s_nk;
    }

    for (int r = tid; r < POST; r += 128) {
        float x1 = 0.0f, y1 = 0.0f, x2 = 0.0f, y2 = 0.0f;
        if (r < nk) {
            int i = s_kept[r];
            float4 b = g_boxes[n*PRE + i];
            x1 = b.x; y1 = b.y; x2 = b.z; y2 = b.w;
        }
        float* o = out + (size_t)(n*POST + r)*5;
        o[1] = x1; o[2] = y1; o[3] = x2; o[4] = y2;
    }

    if (n == 7) {
        for (int r = tid; r < POST; r += 128) {
            float sc = (r < nk) ? g_topk_score[7*PRE + s_kept[r]] : 0.0f;
#pragma unroll
            for (int nn = 0; nn < N_BATCH; ++nn)
                out[(size_t)(nn*POST + r)*5] = sc;
        }
    }
}

// ---------------- launch -----------------------------------------------------
extern "C" void kernel_launch(void* const* d_in, const int* in_sizes, int n_in,
                              void* d_out, int out_size) {
    const float* cls;
    const float* deltas;
    if (in_sizes[0] == N_BATCH*K_ANCH*HW) {     // 1,036,800
        cls = (const float*)d_in[0]; deltas = (const float*)d_in[1];
    } else {
        cls = (const float*)d_in[1]; deltas = (const float*)d_in[0];
    }
    float* out = (float*)d_out;

    hist_kernel<<<dim3(HBLK, N_BATCH), 256>>>(cls);
    compact_kernel<<<dim3(HBLK, N_BATCH), 256>>>(cls);
    rank_kernel<<<dim3(CAND_MAX/8, N_BATCH), 256>>>(deltas);
    dim3 mg((NWORDS + 3)/4, NWORDS, N_BATCH);
    mask_kernel<<<mg, 256>>>();
    scan_kernel<<<N_BATCH, 128>>>(out);
}

// round 16
// speedup vs baseline: 1.3142x; 1.0433x over previous
#include <cuda_runtime.h>
#include <cstdint>

#define N_BATCH 8
#define K_ANCH  9
#define Hdim    120
#define Wdim    120
#define HW      (Hdim*Wdim)
#define TOT     (HW*K_ANCH)       /* 129600 */
#define PRE     3000
#define POST    300
#define NWORDS  47                /* ceil(3000/64) */
#define MPITCH  48
#define NPAIR   24
#define CAND_MAX 8192
#define NBUCKET  4096
#define HBLK     16               /* sweep blocks per batch */

// ---------------- scratch (static device globals; no allocation) ------------
__device__ float  g_topk_score[N_BATCH*PRE];
__device__ float4 g_boxes[N_BATCH*PRE];
__device__ unsigned long long g_mask[(size_t)N_BATCH*PRE*MPITCH];   // ~9.2MB
__device__ unsigned int g_hist[N_BATCH][NBUCKET];     // zeroed by scan_kernel
__device__ unsigned int g_boff[N_BATCH][NBUCKET];     // written by compact blk0
__device__ unsigned int g_bcnt[N_BATCH][NBUCKET];     // zeroed by scan_kernel
__device__ unsigned int g_B[N_BATCH];
__device__ unsigned long long g_cand[N_BATCH][CAND_MAX];

// monotone float->uint key (descending floats -> descending uints)
__device__ __forceinline__ unsigned int fkey(float x) {
    unsigned int u = __float_as_uint(x);
    return (u & 0x80000000u) ? ~u : (u | 0x80000000u);
}
__device__ __forceinline__ float fkey_inv(unsigned int k) {
    return (k & 0x80000000u) ? __uint_as_float(k ^ 0x80000000u)
                             : __uint_as_float(~k);
}
__device__ __forceinline__ float boxarea(float4 b) {
    return __fmul_rn(__fadd_rn(__fsub_rn(b.z, b.x), 1.0f),
                     __fadd_rn(__fsub_rn(b.w, b.y), 1.0f));
}
// exact fp32 test for RN(inter/denom) > 0.5 without division (R9-proven)
__device__ __forceinline__ bool iou_gt_half(float inter, float denom) {
    float t = __fsub_rn(__fadd_rn(inter, inter), denom);
    bool pos = (t > __fmul_rn(denom, 0x1p-24f));
    return (denom > 0.0f) ? pos : ((denom == 0.0f) & (inter > 0.0f));
}
// one suppression test: does box j (bj, aj) get suppressed by row box (bi, ai)
__device__ __forceinline__ bool sup_test(const float4& bi, float ai,
                                         const float4& bj, float aj) {
    float xx1 = fmaxf(bi.x, bj.x), yy1 = fmaxf(bi.y, bj.y);
    float xx2 = fminf(bi.z, bj.z), yy2 = fminf(bi.w, bj.w);
    float iw = fmaxf(__fadd_rn(__fsub_rn(xx2, xx1), 1.0f), 0.0f);
    float ih = fmaxf(__fadd_rn(__fsub_rn(yy2, yy1), 1.0f), 0.0f);
    float inter = __fmul_rn(iw, ih);
    float denom = __fsub_rn(__fadd_rn(ai, aj), inter);
    return iou_gt_half(inter, denom);
}

// ---------------- Stage 1a: chip-wide histogram ------------------------------
extern "C" __global__ void __launch_bounds__(256)
hist_kernel(const float* __restrict__ cls) {
    const int n = blockIdx.y;
    const float4* sc4 = (const float4*)(cls + (size_t)n * TOT);
    unsigned int* h = g_hist[n];
    for (int i = blockIdx.x*256 + threadIdx.x; i < TOT/4; i += HBLK*256) {
        float4 v = sc4[i];
        atomicAdd(&h[fkey(v.x) >> 20], 1u);
        atomicAdd(&h[fkey(v.y) >> 20], 1u);
        atomicAdd(&h[fkey(v.z) >> 20], 1u);
        atomicAdd(&h[fkey(v.w) >> 20], 1u);
    }
}

// ---------------- Stage 1b+1c: per-block threshold + grouped compaction ------
extern "C" __global__ void __launch_bounds__(256)
compact_kernel(const float* __restrict__ cls) {
    const int n   = blockIdx.y;
    const int tid = threadIdx.x;
    __shared__ unsigned int sh_boff[NBUCKET];    // 16KB
    __shared__ unsigned int part[256];
    __shared__ int sB;

    unsigned int h[16];
    const unsigned int base = tid * 16;
#pragma unroll
    for (int q = 0; q < 16; ++q) h[q] = g_hist[n][base + q];
    unsigned int gsum = 0;
#pragma unroll
    for (int q = 0; q < 16; ++q) gsum += h[q];
    part[tid] = gsum;
    if (tid == 0) sB = 0;
    __syncthreads();

    for (int off = 1; off < 256; off <<= 1) {
        unsigned int v = (tid + off < 256) ? part[tid + off] : 0u;
        __syncthreads();
        part[tid] += v;
        __syncthreads();
    }
    unsigned int run = (tid + 1 < 256) ? part[tid + 1] : 0u;
#pragma unroll
    for (int q = 15; q >= 0; --q) {
        sh_boff[base + q] = run;
        if (run + h[q] >= PRE) atomicMax(&sB, (int)(base + q));
        run += h[q];
    }
    __syncthreads();
    const unsigned int B = (unsigned int)sB;

    if (blockIdx.x == 0) {
        for (int b = tid; b < NBUCKET; b += 256) g_boff[n][b] = sh_boff[b];
        if (tid == 0) g_B[n] = B;
    }

    const float4* sc4 = (const float4*)(cls + (size_t)n * TOT);
    for (int i = blockIdx.x*256 + tid; i < TOT/4; i += HBLK*256) {
        float4 v = sc4[i];
        float vv[4] = {v.x, v.y, v.z, v.w};
#pragma unroll
        for (int c = 0; c < 4; ++c) {
            unsigned int k = fkey(vv[c]);
            unsigned int b = k >> 20;
            if (b >= B) {
                unsigned int pos = sh_boff[b] + atomicAdd(&g_bcnt[n][b], 1u);
                if (pos < CAND_MAX)
                    g_cand[n][pos] = ((unsigned long long)k << 32) |
                                     (unsigned int)(~(unsigned int)(4*i + c));
            }
        }
    }
}

// ---------------- Stage 1d+2: warp-per-candidate rank (4x unrolled) ----------
extern "C" __global__ void __launch_bounds__(256)
rank_kernel(const float* __restrict__ deltas) {
    const int n = blockIdx.y;
    const unsigned int B = g_B[n];
    const unsigned int total =
        min(g_boff[n][B] + g_bcnt[n][B], (unsigned)CAND_MAX);
    const unsigned int ci = blockIdx.x*8 + (threadIdx.x >> 5);
    if (ci >= total) return;
    const int lane = threadIdx.x & 31;
    const unsigned FULL = 0xffffffffu;

    const unsigned long long* __restrict__ cand = g_cand[n];
    const unsigned long long mykey = cand[ci];
    const unsigned int b  = (unsigned int)(mykey >> 52);
    const unsigned int lo = g_boff[n][b];
    const unsigned int hi = min(lo + g_bcnt[n][b], (unsigned)CAND_MAX);

    int c = 0;
    unsigned int j = lo + lane;
    for (; j + 96 < hi; j += 128) {
        c += (cand[j     ] > mykey);
        c += (cand[j + 32] > mykey);
        c += (cand[j + 64] > mykey);
        c += (cand[j + 96] > mykey);
    }
    for (; j < hi; j += 32) c += (cand[j] > mykey);
    unsigned int rank = lo + __reduce_add_sync(FULL, c);
    if (rank >= PRE || lane != 0) return;

    unsigned int key = (unsigned int)(mykey >> 32);
    int o = (int)(~(unsigned int)(mykey & 0xFFFFFFFFull));
    g_topk_score[n*PRE + rank] = fkey_inv(key);

    const float ratios_[3] = {0.5f, 1.0f, 2.0f};
    const float scales_[3] = {8.0f, 16.0f, 32.0f};
    const int kk = o % K_ANCH;
    const int t0 = o / K_ANCH;
    const int ww = t0 % Wdim;
    const int hh = t0 / Wdim;

    float v[4];
#pragma unroll
    for (int jj = 0; jj < 4; ++jj) {
        int f  = ((kk*4 + jj)*Hdim + hh)*Wdim + ww;
        int jq = f & 3;
        int r1 = f >> 2;
        int k  = r1 % K_ANCH;
        int r2 = r1 / K_ANCH;
        int w  = r2 % Wdim;
        int hq = r2 / Wdim;

        float sr  = __fsqrt_rn(ratios_[k/3]);
        float wsz = __fdiv_rn(__fmul_rn(16.0f, scales_[k%3]), sr);
        float hsz = __fmul_rn(__fmul_rn(16.0f, scales_[k%3]), sr);
        float cx  = __fmul_rn(__fadd_rn((float)w, 0.5f), 16.0f);
        float cy  = __fmul_rn(__fadd_rn((float)hq, 0.5f), 16.0f);

        float a;
        if      (jq == 0) a = __fsub_rn(cx, __fmul_rn(0.5f, wsz));
        else if (jq == 1) a = __fsub_rn(cy, __fmul_rn(0.5f, hsz));
        else if (jq == 2) a = __fadd_rn(cx, __fmul_rn(0.5f, wsz));
        else              a = __fadd_rn(cy, __fmul_rn(0.5f, hsz));

        float d   = deltas[((size_t)n*36 + (k*4 + jq))*HW + hq*Wdim + w];
        float val = __fadd_rn(a, d);
        v[jj] = fminf(fmaxf(val, 0.0f), 1919.0f);
    }
    g_boxes[n*PRE + rank] = make_float4(v[0], v[1], v[2], v[3]);
}

// ---------------- Stage 3: NMS suppression bitmask (specialized tiles) -------
// Interior tiles (rb < cb, cb not ragged): fully unrolled 64-column loop with
// immediate-shift bit accumulation into two 32-bit halves. Diagonal / last
// column block keep the generic loop. IoU math identical to R9.
extern "C" __global__ void __launch_bounds__(256)
mask_kernel() {
    const int cb = blockIdx.y, n = blockIdx.z;
    const int sub = threadIdx.x >> 6;
    const int t   = threadIdx.x & 63;
    const int rb  = blockIdx.x*4 + sub;
    __shared__ float4 colbox[64];
    __shared__ float  colarea[64];

    if (threadIdx.x < 64) {
        int cj = cb*64 + threadIdx.x;
        float4 cbx = (cj < PRE) ? g_boxes[n*PRE + cj] : make_float4(0,0,0,0);
        colbox[threadIdx.x]  = cbx;
        colarea[threadIdx.x] = boxarea(cbx);
    }
    __syncthreads();

    if (rb > cb || rb >= NWORDS) return;
    const int i = rb*64 + t;
    if (i >= PRE) return;

    const float4 bi = g_boxes[n*PRE + i];
    const float  ai = boxarea(bi);
    unsigned long long bits;

    if (rb < cb && cb < NWORDS - 1) {
        // ---- interior tile: full 64 columns, unrolled, immediate shifts ----
        unsigned int blo = 0u, bhi = 0u;
#pragma unroll
        for (int c = 0; c < 32; ++c)
            if (sup_test(bi, ai, colbox[c], colarea[c])) blo |= (1u << c);
#pragma unroll
        for (int c = 0; c < 32; ++c)
            if (sup_test(bi, ai, colbox[32 + c], colarea[32 + c]))
                bhi |= (1u << c);
        bits = ((unsigned long long)bhi << 32) | blo;
    } else {
        // ---- diagonal or ragged last column block: generic loop ----
        const int jmax = min(64, PRE - cb*64);
        const int cstart = (rb == cb) ? (t + 1) : 0;
        bits = 0ull;
        for (int c = cstart; c < jmax; ++c)
            if (sup_test(bi, ai, colbox[c], colarea[c]))
                bits |= (1ull << c);
    }
    g_mask[((size_t)n*PRE + i)*MPITCH + cb] = bits;
}

// ---------------- Stage 4: lazy scan, 4 warps/batch (R10-proven) -------------
extern "C" __global__ void __launch_bounds__(128)
scan_kernel(float* __restrict__ out) {
    const int n = blockIdx.x;
    const int tid  = threadIdx.x;
    const int lane = tid & 31;
    const int wid  = tid >> 5;
    __shared__ ulonglong2 s_diag[2][128];
    __shared__ ulonglong2 s_accw[4];
    __shared__ int s_kept[POST];
    __shared__ int s_nk;
    const unsigned FULL = 0xffffffffu;

    for (int b = tid; b < NBUCKET; b += 128) {
        g_bcnt[n][b] = 0;
        g_hist[n][b] = 0;
    }

    const unsigned long long* __restrict__ mbase =
        g_mask + (size_t)n * PRE * MPITCH;

    s_diag[0][tid] = *(const ulonglong2*)(mbase + (size_t)tid * MPITCH);

    int nk = 0;
    for (int t = 0; t < NPAIR && nk < POST; ++t) {
        const int cb = t & 1, pb = cb ^ 1;
        const int w2 = 2*t;

        if (t + 1 < NPAIR) {
            int r = 128*(t+1) + tid;
            ulonglong2 d = make_ulonglong2(0ull, 0ull);
            if (r < PRE)
                d = *(const ulonglong2*)(mbase + (size_t)r * MPITCH + (w2+2));
            s_diag[pb][tid] = d;
        }

        unsigned long long gx = 0ull, gy = 0ull;
        for (int j = tid; j < nk; j += 128) {
            ulonglong2 m = *(const ulonglong2*)
                (mbase + (size_t)s_kept[j] * MPITCH + w2);
            gx |= m.x; gy |= m.y;
        }
#pragma unroll
        for (int off = 16; off; off >>= 1) {
            gx |= __shfl_xor_sync(FULL, gx, off);
            gy |= __shfl_xor_sync(FULL, gy, off);
        }
        if (lane == 0) s_accw[wid] = make_ulonglong2(gx, gy);
        __syncthreads();

        if (wid == 0) {
            unsigned long long a0 =
                s_accw[0].x | s_accw[1].x | s_accw[2].x | s_accw[3].x;
            unsigned long long a1 =
                s_accw[0].y | s_accw[1].y | s_accw[2].y | s_accw[3].y;
            unsigned long long f0 = (w2   == NWORDS-1) ? ((1ull<<56)-1ull)
                                  : (w2   <  NWORDS  ) ? ~0ull : 0ull;
            unsigned long long f1 = (w2+1 == NWORDS-1) ? ((1ull<<56)-1ull)
                                  : (w2+1 <  NWORDS  ) ? ~0ull : 0ull;
            unsigned long long c0 = f0 & ~a0;
            unsigned long long c1 = f1 & ~a1;

            const int base = 128*t;
            int k = nk;
            while ((c0 | c1) && k < POST) {
                if (c0) {
                    int b = __ffsll((long long)c0) - 1;
                    s_kept[k] = base + b;
                    ++k;
                    c0 &= ~(1ull << b);
                    ulonglong2 d = s_diag[cb][b];
                    c0 &= ~d.x;
                    c1 &= ~d.y;
                } else {
                    int b = __ffsll((long long)c1) - 1;
                    s_kept[k] = base + 64 + b;
                    ++k;
                    c1 &= ~(1ull << b);
                    ulonglong2 d = s_diag[cb][64 + b];
                    c1 &= ~d.y;
                }
            }
            if (lane == 0) s_nk = k;
        }
        __syncthreads();
        nk = s_nk;
    }

    for (int r = tid; r < POST; r += 128) {
        float x1 = 0.0f, y1 = 0.0f, x2 = 0.0f, y2 = 0.0f;
        if (r < nk) {
            int i = s_kept[r];
            float4 b = g_boxes[n*PRE + i];
            x1 = b.x; y1 = b.y; x2 = b.z; y2 = b.w;
        }
        float* o = out + (size_t)(n*POST + r)*5;
        o[1] = x1; o[2] = y1; o[3] = x2; o[4] = y2;
    }

    if (n == 7) {
        for (int r = tid; r < POST; r += 128) {
            float sc = (r < nk) ? g_topk_score[7*PRE + s_kept[r]] : 0.0f;
#pragma unroll
            for (int nn = 0; nn < N_BATCH; ++nn)
                out[(size_t)(nn*POST + r)*5] = sc;
        }
    }
}

// ---------------- launch -----------------------------------------------------
extern "C" void kernel_launch(void* const* d_in, const int* in_sizes, int n_in,
                              void* d_out, int out_size) {
    const float* cls;
    const float* deltas;
    if (in_sizes[0] == N_BATCH*K_ANCH*HW) {     // 1,036,800
        cls = (const float*)d_in[0]; deltas = (const float*)d_in[1];
    } else {
        cls = (const float*)d_in[1]; deltas = (const float*)d_in[0];
    }
    float* out = (float*)d_out;

    hist_kernel<<<dim3(HBLK, N_BATCH), 256>>>(cls);
    compact_kernel<<<dim3(HBLK, N_BATCH), 256>>>(cls);
    rank_kernel<<<dim3(CAND_MAX/8, N_BATCH), 256>>>(deltas);
    dim3 mg((NWORDS + 3)/4, NWORDS, N_BATCH);
    mask_kernel<<<mg, 256>>>();
    scan_kernel<<<N_BATCH, 128>>>(out);
}